// round 15
// baseline (speedup 1.0000x reference)
#include <cuda_runtime.h>

#define B 4
#define L 2048
#define H 8
#define D 64
#define S 40
#define NTOP 40
#define BH (B*H)

#define KS 8            // k-splits (256 keys each)
#define NU 8            // u-chunks
#define UPC 5           // u rows per chunk

#define CCH 64          // cumsum chunks
#define CLEN (L/CCH)    // 32 rows per chunk

#define NCH 8           // k-chunks (and l-chunks) for mscore tiling
#define CELLCAP 2048    // max pairs per cell (mean 1280, 4-sigma ~1430)

#define ATT_BLOCKS (KS*NU*BH)   // 2048

#define FULLMASK 0xffffffffu

// Scratch (no allocations allowed)
__device__ unsigned char g_list[NCH * NCH * CELLCAP];  // [lc][kc][pairs] ki&255
__device__ int   g_cnt[L * NCH];                       // [l][kc]
__device__ int   g_offs[L * NCH];                      // [l][kc] within-cell start
__device__ float g_pmx[BH * NCH * L];                  // per-(bh,kc) partial max
__device__ float g_psm[BH * NCH * L];                  // per-(bh,kc) partial sum
__device__ int   g_top[BH * NTOP];
__device__ float g_cs[BH * CCH * D];
__device__ float g_pl[BH * NTOP * KS];
__device__ float g_pacc[BH * NTOP * KS * D];

__device__ __forceinline__ float4 f4add(float4 a, float4 b) {
    return make_float4(a.x + b.x, a.y + b.y, a.z + b.z, a.w + b.w);
}

// ---------------------------------------------------------------------------
// K0: binprep ∪ cumsumA (independent roles, block-uniform branch).
// binprep (blocks [0,8), block = lc, thread = l within chunk): count samples
//   per kc, exclusive block-scan per kc for within-cell offsets, scatter
//   ki&255 bytes into cell lists. Fully deterministic (no atomics).
// cumsumA (blocks [8, 8+CCH*BH/2)): per-chunk V sums, 2 chunks per block.
// index_sample is int32 on the wire (JAX x64-disabled downcast).
// ---------------------------------------------------------------------------
__global__ void __launch_bounds__(256)
k0_binprep_cumsumA(const int* __restrict__ idx, const float* __restrict__ V) {
    __shared__ int sc[256];
    __shared__ float4 sa[2][8][16];
    int tid = threadIdx.x;

    if (blockIdx.x < NCH) {
        // ------------------- binprep -------------------
        int lc = blockIdx.x;
        int l = lc * 256 + tid;
        const int* srow = idx + (size_t)l * S;

        int c[NCH];
        #pragma unroll
        for (int k = 0; k < NCH; k++) c[k] = 0;
        for (int s = 0; s < S; s++) c[srow[s] >> 8]++;

        #pragma unroll
        for (int k = 0; k < NCH; k++) g_cnt[l * NCH + k] = c[k];

        int off[NCH];
        #pragma unroll
        for (int k = 0; k < NCH; k++) {
            sc[tid] = c[k];
            __syncthreads();
            for (int dd = 1; dd < 256; dd <<= 1) {
                int t = (tid >= dd) ? sc[tid - dd] : 0;
                __syncthreads();
                sc[tid] += t;
                __syncthreads();
            }
            off[k] = sc[tid] - c[k];      // exclusive
            __syncthreads();
        }
        #pragma unroll
        for (int k = 0; k < NCH; k++) g_offs[l * NCH + k] = off[k];

        int r[NCH];
        #pragma unroll
        for (int k = 0; k < NCH; k++) r[k] = 0;
        for (int s = 0; s < S; s++) {
            int ki = srow[s];
            int kc = ki >> 8;
            g_list[(size_t)(lc * NCH + kc) * CELLCAP + off[kc] + r[kc]] = (unsigned char)(ki & 255);
            r[kc]++;
        }
    } else {
        // ------------------- cumsumA -------------------
        int cb = blockIdx.x - NCH;
        int half = tid >> 7;
        int t = tid & 127;
        int cc2 = cb * 2 + half;
        int c = cc2 & (CCH - 1), bh = cc2 >> 6;
        int b = bh >> 3, h = bh & 7;
        int rg = t >> 4, f4 = t & 15;
        const int RS = H * D / 4;

        const float4* vb = (const float4*)(V + ((size_t)(b * L + c * CLEN + rg * 4) * H + h) * D) + f4;
        float4 s = vb[0];
        #pragma unroll
        for (int i = 1; i < 4; i++) s = f4add(s, vb[(size_t)i * RS]);

        sa[half][rg][f4] = s;
        __syncthreads();
        if (rg == 0) {
            float4 tt = sa[half][0][f4];
            #pragma unroll
            for (int i = 1; i < 8; i++) tt = f4add(tt, sa[half][i][f4]);
            ((float4*)g_cs)[(bh * CCH + c) * 16 + f4] = tt;
        }
    }
}

// ---------------------------------------------------------------------------
// K1: mscore2 — tiled sampled-score partials. grid (64 cells, 32 bh), 256 thr,
// 64KB dyn smem = K rows of this cell's kc chunk (3 blocks/SM).
// 32 groups of 8 lanes; group owns 8 consecutive l's of the lc chunk: loads
// Q[l] once into regs (double-buffered prefetch), streams its in-cell samples
// from smem (broadcast byte index; conflict-free LDS.128). Per-(bh,kc,l)
// partial max/sum written to disjoint slots — deterministic, no atomics.
// ---------------------------------------------------------------------------
extern __shared__ float Ks2[];   // 256 rows * 64 floats = 64KB

__global__ void __launch_bounds__(256)
mscore2_kernel(const float* __restrict__ Q, const float* __restrict__ K) {
    int cell = blockIdx.x;             // lc*8 + kc
    int lc = cell >> 3, kc = cell & 7;
    int bh = blockIdx.y;
    int b = bh >> 3, h = bh & 7;
    int tid = threadIdx.x, w = tid >> 5, lane = tid & 31;
    int g = lane >> 3, j = lane & 7;

    {   // stage K chunk (coalesced)
        int f4 = tid & 15, r0 = tid >> 4;
        const float4* kg = (const float4*)(K + ((size_t)(b * L + kc * 256) * H + h) * D);
        float4* ks4w = (float4*)Ks2;
        #pragma unroll
        for (int i = 0; i < 16; i++) {
            int r = r0 + 16 * i;
            ks4w[r * 16 + f4] = kg[(size_t)r * (H * D / 4) + f4];
        }
    }
    __syncthreads();

    const float4* ks4 = (const float4*)Ks2;
    int grp = w * 4 + g;               // 0..31
    int l0 = lc * 256 + grp * 8;
    const float* Qb = Q + ((size_t)b * L * H + h) * D;
    const unsigned char* cl = g_list + (size_t)cell * CELLCAP;

    // prefetch first l's Q slice
    const float4* q4 = (const float4*)(Qb + (size_t)l0 * H * D);
    float4 qa = q4[j], qb = q4[8 + j];

    float* pmx = g_pmx + ((size_t)bh * NCH + kc) * L;
    float* psm = g_psm + ((size_t)bh * NCH + kc) * L;

    for (int il = 0; il < 8; il++) {
        int l = l0 + il;
        int cnt = g_cnt[l * NCH + kc];
        int off = g_offs[l * NCH + kc];

        float4 qa_n, qb_n;
        if (il < 7) {   // prefetch next l (guarded: l+1 stays in-bounds)
            const float4* qn = (const float4*)(Qb + (size_t)(l + 1) * H * D);
            qa_n = qn[j]; qb_n = qn[8 + j];
        }

        float mx = -1e30f, sm = 0.f;
        for (int e = 0; e < cnt; e++) {
            int kil = cl[off + e];                 // broadcast to 8 lanes
            float4 ka = ks4[kil * 16 + j], kb = ks4[kil * 16 + 8 + j];
            float d = qa.x*ka.x + qa.y*ka.y + qa.z*ka.z + qa.w*ka.w
                    + qb.x*kb.x + qb.y*kb.y + qb.z*kb.z + qb.w*kb.w;
            d += __shfl_down_sync(FULLMASK, d, 4);
            d += __shfl_down_sync(FULLMASK, d, 2);
            d += __shfl_down_sync(FULLMASK, d, 1);
            if (j == 0) { mx = fmaxf(mx, d); sm += d; }
        }
        if (j == 0) { pmx[l] = mx; psm[l] = sm; }

        qa = qa_n; qb = qb_n;
    }
}

// ---------------------------------------------------------------------------
// K2: topk ∪ cumsumC (block-uniform branch; shared pool).
// topk (blocks [0,BH)): combine the NCH kc-partials into M on load, then 40
//   block-argmax passes; emits the selected set ASCENDING (order-invariant).
// cumsumC (blocks [BH, +CCH*BH)): scan, 16 subgroups x 2 rows.
// ---------------------------------------------------------------------------
__global__ void __launch_bounds__(256)
k2_topk_cumsumC(const float* __restrict__ V, float* __restrict__ out) {
    __shared__ __align__(16) char pool[8448];
    int tid = threadIdx.x;

    if (blockIdx.x < BH) {
        // ------------------- topk -------------------
        float* vals = (float*)pool;             // 2048 floats
        float* wv   = (float*)(pool + 8192);    // 8
        int*   wi   = (int*)(pool + 8224);      // 8
        int*   sel  = (int*)(pool + 8256);      // 40
        int bh = blockIdx.x;

        const float* pmx = g_pmx + (size_t)bh * NCH * L;
        const float* psm = g_psm + (size_t)bh * NCH * L;
        for (int i = tid; i < L; i += 256) {
            float mx = -1e30f, sm = 0.f;
            #pragma unroll
            for (int c = 0; c < NCH; c++) {
                mx = fmaxf(mx, pmx[c * L + i]);
                sm += psm[c * L + i];
            }
            vals[i] = mx - sm * (1.0f / (float)L);
        }
        __syncthreads();

        for (int t = 0; t < NTOP; t++) {
            float bv = -1e38f; int bi = 0;
            for (int i = tid; i < L; i += 256) {
                float v = vals[i];
                if (v > bv) { bv = v; bi = i; }
            }
            #pragma unroll
            for (int off = 16; off; off >>= 1) {
                float ov = __shfl_down_sync(FULLMASK, bv, off);
                int   oi = __shfl_down_sync(FULLMASK, bi, off);
                if (ov > bv || (ov == bv && oi < bi)) { bv = ov; bi = oi; }
            }
            if ((tid & 31) == 0) { wv[tid >> 5] = bv; wi[tid >> 5] = bi; }
            __syncthreads();
            if (tid == 0) {
                float fv = wv[0]; int fi = wi[0];
                #pragma unroll
                for (int ww = 1; ww < 8; ww++)
                    if (wv[ww] > fv || (wv[ww] == fv && wi[ww] < fi)) { fv = wv[ww]; fi = wi[ww]; }
                sel[t] = fi;
                vals[fi] = -1e38f;
            }
            __syncthreads();
        }

        if (tid < NTOP) {
            int mine = sel[tid], r = 0;
            #pragma unroll
            for (int i = 0; i < NTOP; i++) r += (sel[i] < mine);
            g_top[bh * NTOP + r] = mine;
        }
    } else {
        // ------------------- cumsumC -------------------
        float4 (*sp)[16] = (float4(*)[16])pool;            // [16][16]
        float4 (*sg)[16] = (float4(*)[16])(pool + 4096);   // [16][16]
        int cb = blockIdx.x - BH;
        int c = cb & (CCH - 1), bh = cb >> 6;
        int b = bh >> 3, h = bh & 7;
        int rg = tid >> 4, f4 = tid & 15;
        const int RS = H * D / 4;

        const float4* vb = (const float4*)(V + ((size_t)(b * L + c * CLEN + rg * 2) * H + h) * D) + f4;
        float4 v0 = vb[0], v1 = vb[RS];
        sp[rg][f4] = f4add(v0, v1);

        float4 gacc = make_float4(0.f, 0.f, 0.f, 0.f);
        const float4* cs4 = (const float4*)g_cs + (size_t)bh * CCH * 16 + f4;
        for (int cc = rg; cc < c; cc += 16) gacc = f4add(gacc, cs4[cc * 16]);
        sg[rg][f4] = gacc;
        __syncthreads();

        float4 run = make_float4(0.f, 0.f, 0.f, 0.f);
        #pragma unroll
        for (int i = 0; i < 16; i++) {
            run = f4add(run, sg[i][f4]);
            if (i < rg) run = f4add(run, sp[i][f4]);
        }

        float4 o0 = f4add(run, v0);
        float4 o1 = f4add(o0, v1);

        float4* ob = (float4*)(out + ((size_t)bh * L + c * CLEN + rg * 2) * D) + f4;
        ob[0] = o0; ob[16] = o1;
    }
}

// ---------------------------------------------------------------------------
// K3: attention partials, UNNORMALIZED exp (|s|<~6 so exp can't overflow;
// Σp·v/Σp identical to softmax). grid (KS, NU, BH). Causal early exit.
// ---------------------------------------------------------------------------
__global__ void __launch_bounds__(256)
attn_part_kernel(const float* __restrict__ Q,
                 const float* __restrict__ K,
                 const float* __restrict__ V) {
    int ks = blockIdx.x, uc = blockIdx.y, bh = blockIdx.z;
    int b = bh >> 3, h = bh & 7;
    int u0 = uc * UPC;

    int lu[UPC];
    #pragma unroll
    for (int iu = 0; iu < UPC; iu++) lu[iu] = g_top[bh * NTOP + u0 + iu];
    int lu_hi = lu[UPC - 1];
    if (ks * 256 > lu_hi) return;          // causal early exit

    int tid = threadIdx.x, w = tid >> 5, lane = tid & 31;
    int g = lane >> 3, j = lane & 7;

    float4 qa[UPC], qb[UPC];
    #pragma unroll
    for (int iu = 0; iu < UPC; iu++) {
        const float4* q4 = (const float4*)(Q + ((size_t)(b * L + lu[iu]) * H + h) * D);
        qa[iu] = q4[j]; qb[iu] = q4[8 + j];
    }

    float lsum[UPC];
    float4 aa[UPC], ab[UPC];
    #pragma unroll
    for (int iu = 0; iu < UPC; iu++) {
        lsum[iu] = 0.f;
        aa[iu] = make_float4(0.f, 0.f, 0.f, 0.f);
        ab[iu] = make_float4(0.f, 0.f, 0.f, 0.f);
    }

    int base = ks * 256 + w * 32;
    int nst = 0;
    if (base <= lu_hi) {
        int span = lu_hi + 1 - base;
        if (span > 32) span = 32;
        nst = (span + 3) >> 2;
    }

    const float* Kb = K + ((size_t)b * L * H + h) * D;
    const float* Vb = V + ((size_t)b * L * H + h) * D;

    for (int st = 0; st < nst; st++) {
        int t = base + st * 4 + g;
        const float4* k4 = (const float4*)(Kb + (size_t)t * H * D);
        const float4* v4 = (const float4*)(Vb + (size_t)t * H * D);
        float4 ka = k4[j], kb = k4[8 + j];
        float4 va = v4[j], vb = v4[8 + j];

        #pragma unroll
        for (int iu = 0; iu < UPC; iu++) {
            float d = qa[iu].x*ka.x + qa[iu].y*ka.y + qa[iu].z*ka.z + qa[iu].w*ka.w
                    + qb[iu].x*kb.x + qb[iu].y*kb.y + qb[iu].z*kb.z + qb[iu].w*kb.w;
            d += __shfl_xor_sync(FULLMASK, d, 4);
            d += __shfl_xor_sync(FULLMASK, d, 2);
            d += __shfl_xor_sync(FULLMASK, d, 1);
            float s = (t <= lu[iu]) ? d * 0.125f : -3e38f;
            float p = __expf(s);
            lsum[iu] += p;
            aa[iu].x += p * va.x; aa[iu].y += p * va.y;
            aa[iu].z += p * va.z; aa[iu].w += p * va.w;
            ab[iu].x += p * vb.x; ab[iu].y += p * vb.y;
            ab[iu].z += p * vb.z; ab[iu].w += p * vb.w;
        }
    }

    __shared__ float s_l[UPC][32];
    __shared__ float s_acc[UPC][32][64];
    int gs = w * 4 + g;
    #pragma unroll
    for (int iu = 0; iu < UPC; iu++) {
        if (j == 0) s_l[iu][gs] = lsum[iu];
        *(float4*)&s_acc[iu][gs][4 * j]      = aa[iu];
        *(float4*)&s_acc[iu][gs][32 + 4 * j] = ab[iu];
    }
    __syncthreads();

    for (int i = tid; i < UPC * 64; i += 256) {
        int iu = i >> 6, d = i & 63;
        float a = 0.f;
        #pragma unroll
        for (int gsi = 0; gsi < 32; gsi++) a += s_acc[iu][gsi][d];
        g_pacc[((size_t)(bh * NTOP + u0 + iu) * KS + ks) * D + d] = a;
    }
    if (tid < UPC) {
        float lt = 0.f;
        #pragma unroll
        for (int gsi = 0; gsi < 32; gsi++) lt += s_l[tid][gsi];
        g_pl[(size_t)(bh * NTOP + u0 + tid) * KS + ks] = lt;
    }
}

// ---------------------------------------------------------------------------
// K4: combine valid ks partials, normalize, scatter. grid (10, BH), 256 thr.
// ---------------------------------------------------------------------------
__global__ void __launch_bounds__(256)
attn_combine_kernel(float* __restrict__ out) {
    int bh = blockIdx.y;
    int tid = threadIdx.x;
    int u = blockIdx.x * 4 + (tid >> 6);
    int d = tid & 63;

    int uc = u / UPC;
    int lu_hi = g_top[bh * NTOP + uc * UPC + (UPC - 1)];
    int nks = (lu_hi >> 8) + 1;

    size_t base = (size_t)(bh * NTOP + u) * KS;
    float acc = 0.f, lt = 0.f;
    for (int p = 0; p < nks; p++) {
        acc += g_pacc[(base + p) * D + d];
        lt  += g_pl[base + p];
    }
    int lu = g_top[bh * NTOP + u];
    out[((size_t)bh * L + lu) * D + d] = acc / lt;
}

// ---------------------------------------------------------------------------
extern "C" void kernel_launch(void* const* d_in, const int* in_sizes, int n_in,
                              void* d_out, int out_size) {
    const float* Q   = (const float*)d_in[0];
    const float* K   = (const float*)d_in[1];
    const float* V   = (const float*)d_in[2];
    const int*   idx = (const int*)d_in[3];
    float*       out = (float*)d_out;

    const int KSMEM = 256 * D * sizeof(float);   // 64 KB
    cudaFuncSetAttribute(mscore2_kernel,
                         cudaFuncAttributeMaxDynamicSharedMemorySize, KSMEM);

    k0_binprep_cumsumA<<<NCH + CCH * BH / 2, 256>>>(idx, V);
    mscore2_kernel<<<dim3(NCH * NCH, BH), 256, KSMEM>>>(Q, K);
    k2_topk_cumsumC<<<BH + CCH * BH, 256>>>(V, out);
    attn_part_kernel<<<dim3(KS, NU, BH), 256>>>(Q, K, V);
    attn_combine_kernel<<<dim3(10, BH), 256>>>(out);
}

// round 16
// speedup vs baseline: 1.0010x; 1.0010x over previous
#include <cuda_runtime.h>

#define B 4
#define L 2048
#define H 8
#define D 64
#define S 40
#define NTOP 40
#define BH (B*H)

#define KS 8            // k-splits (256 keys each)
#define NU 8            // u-chunks
#define UPC 5           // u rows per chunk

#define CCH 64          // cumsum chunks
#define CLEN (L/CCH)    // 32 rows per chunk

#define NCH 8           // k-chunks (and l-chunks) for mscore tiling
#define CELLCAP 2048    // max pairs per cell (mean 1280, 4-sigma ~1430)

#define ATT_BLOCKS (KS*NU*BH)   // 2048

#define FULLMASK 0xffffffffu

// Scratch (no allocations allowed)
__device__ unsigned char g_list[NCH * NCH * CELLCAP];  // [lc][kc][pairs] ki&255
__device__ int   g_cnt[L * NCH];                       // [l][kc]
__device__ int   g_offs[L * NCH];                      // [l][kc] within-cell start
__device__ float g_pmx[BH * NCH * L];                  // per-(bh,kc) partial max
__device__ float g_psm[BH * NCH * L];                  // per-(bh,kc) partial sum
__device__ int   g_top[BH * NTOP];
__device__ float g_cs[BH * CCH * D];
__device__ float g_pl[BH * NTOP * KS];
__device__ float g_pacc[BH * NTOP * KS * D];

__device__ __forceinline__ float4 f4add(float4 a, float4 b) {
    return make_float4(a.x + b.x, a.y + b.y, a.z + b.z, a.w + b.w);
}

// ---------------------------------------------------------------------------
// K0: binprep ∪ cumsumA (independent roles, block-uniform branch).
// binprep (blocks [0,8), block = lc, thread = l within chunk): count samples
//   per kc, exclusive block-scan per kc for within-cell offsets, scatter
//   ki&255 bytes into cell lists. Fully deterministic (no atomics).
// cumsumA (blocks [8, 8+CCH*BH/2)): per-chunk V sums, 2 chunks per block.
// index_sample is int32 on the wire (JAX x64-disabled downcast).
// ---------------------------------------------------------------------------
__global__ void __launch_bounds__(256)
k0_binprep_cumsumA(const int* __restrict__ idx, const float* __restrict__ V) {
    __shared__ int sc[256];
    __shared__ float4 sa[2][8][16];
    int tid = threadIdx.x;

    if (blockIdx.x < NCH) {
        // ------------------- binprep -------------------
        int lc = blockIdx.x;
        int l = lc * 256 + tid;
        const int* srow = idx + (size_t)l * S;

        int c[NCH];
        #pragma unroll
        for (int k = 0; k < NCH; k++) c[k] = 0;
        for (int s = 0; s < S; s++) c[srow[s] >> 8]++;

        #pragma unroll
        for (int k = 0; k < NCH; k++) g_cnt[l * NCH + k] = c[k];

        int off[NCH];
        #pragma unroll
        for (int k = 0; k < NCH; k++) {
            sc[tid] = c[k];
            __syncthreads();
            for (int dd = 1; dd < 256; dd <<= 1) {
                int t = (tid >= dd) ? sc[tid - dd] : 0;
                __syncthreads();
                sc[tid] += t;
                __syncthreads();
            }
            off[k] = sc[tid] - c[k];      // exclusive
            __syncthreads();
        }
        #pragma unroll
        for (int k = 0; k < NCH; k++) g_offs[l * NCH + k] = off[k];

        int r[NCH];
        #pragma unroll
        for (int k = 0; k < NCH; k++) r[k] = 0;
        for (int s = 0; s < S; s++) {
            int ki = srow[s];
            int kc = ki >> 8;
            g_list[(size_t)(lc * NCH + kc) * CELLCAP + off[kc] + r[kc]] = (unsigned char)(ki & 255);
            r[kc]++;
        }
    } else {
        // ------------------- cumsumA -------------------
        int cb = blockIdx.x - NCH;
        int half = tid >> 7;
        int t = tid & 127;
        int cc2 = cb * 2 + half;
        int c = cc2 & (CCH - 1), bh = cc2 >> 6;
        int b = bh >> 3, h = bh & 7;
        int rg = t >> 4, f4 = t & 15;
        const int RS = H * D / 4;

        const float4* vb = (const float4*)(V + ((size_t)(b * L + c * CLEN + rg * 4) * H + h) * D) + f4;
        float4 s = vb[0];
        #pragma unroll
        for (int i = 1; i < 4; i++) s = f4add(s, vb[(size_t)i * RS]);

        sa[half][rg][f4] = s;
        __syncthreads();
        if (rg == 0) {
            float4 tt = sa[half][0][f4];
            #pragma unroll
            for (int i = 1; i < 8; i++) tt = f4add(tt, sa[half][i][f4]);
            ((float4*)g_cs)[(bh * CCH + c) * 16 + f4] = tt;
        }
    }
}

// ---------------------------------------------------------------------------
// K1: mscore2 — tiled sampled-score partials. grid (64 cells, 32 bh), 256 thr,
// 64KB dyn smem = K rows of this cell's kc chunk (3 blocks/SM).
// 32 groups of 8 lanes; group owns 8 consecutive l's of the lc chunk: loads
// Q[l] once into regs (double-buffered prefetch), streams its in-cell samples
// from smem (broadcast byte index; conflict-free LDS.128). Per-(bh,kc,l)
// partial max/sum written to disjoint slots — deterministic, no atomics.
// ---------------------------------------------------------------------------
extern __shared__ float Ks2[];   // 256 rows * 64 floats = 64KB

__global__ void __launch_bounds__(256)
mscore2_kernel(const float* __restrict__ Q, const float* __restrict__ K) {
    int cell = blockIdx.x;             // lc*8 + kc
    int lc = cell >> 3, kc = cell & 7;
    int bh = blockIdx.y;
    int b = bh >> 3, h = bh & 7;
    int tid = threadIdx.x, w = tid >> 5, lane = tid & 31;
    int g = lane >> 3, j = lane & 7;

    {   // stage K chunk (coalesced)
        int f4 = tid & 15, r0 = tid >> 4;
        const float4* kg = (const float4*)(K + ((size_t)(b * L + kc * 256) * H + h) * D);
        float4* ks4w = (float4*)Ks2;
        #pragma unroll
        for (int i = 0; i < 16; i++) {
            int r = r0 + 16 * i;
            ks4w[r * 16 + f4] = kg[(size_t)r * (H * D / 4) + f4];
        }
    }
    __syncthreads();

    const float4* ks4 = (const float4*)Ks2;
    int grp = w * 4 + g;               // 0..31
    int l0 = lc * 256 + grp * 8;
    const float* Qb = Q + ((size_t)b * L * H + h) * D;
    const unsigned char* cl = g_list + (size_t)cell * CELLCAP;

    // prefetch first l's Q slice
    const float4* q4 = (const float4*)(Qb + (size_t)l0 * H * D);
    float4 qa = q4[j], qb = q4[8 + j];

    float* pmx = g_pmx + ((size_t)bh * NCH + kc) * L;
    float* psm = g_psm + ((size_t)bh * NCH + kc) * L;

    for (int il = 0; il < 8; il++) {
        int l = l0 + il;
        int cnt = g_cnt[l * NCH + kc];
        int off = g_offs[l * NCH + kc];

        float4 qa_n, qb_n;
        if (il < 7) {   // prefetch next l (guarded: l+1 stays in-bounds)
            const float4* qn = (const float4*)(Qb + (size_t)(l + 1) * H * D);
            qa_n = qn[j]; qb_n = qn[8 + j];
        }

        float mx = -1e30f, sm = 0.f;
        for (int e = 0; e < cnt; e++) {
            int kil = cl[off + e];                 // broadcast to 8 lanes
            float4 ka = ks4[kil * 16 + j], kb = ks4[kil * 16 + 8 + j];
            float d = qa.x*ka.x + qa.y*ka.y + qa.z*ka.z + qa.w*ka.w
                    + qb.x*kb.x + qb.y*kb.y + qb.z*kb.z + qb.w*kb.w;
            d += __shfl_down_sync(FULLMASK, d, 4);
            d += __shfl_down_sync(FULLMASK, d, 2);
            d += __shfl_down_sync(FULLMASK, d, 1);
            if (j == 0) { mx = fmaxf(mx, d); sm += d; }
        }
        if (j == 0) { pmx[l] = mx; psm[l] = sm; }

        qa = qa_n; qb = qb_n;
    }
}

// ---------------------------------------------------------------------------
// K2: topk ∪ cumsumC (block-uniform branch; shared pool).
// topk (blocks [0,BH)): combine the NCH kc-partials into M on load, then 40
//   block-argmax passes; emits the selected set ASCENDING (order-invariant).
// cumsumC (blocks [BH, +CCH*BH)): scan, 16 subgroups x 2 rows.
// ---------------------------------------------------------------------------
__global__ void __launch_bounds__(256)
k2_topk_cumsumC(const float* __restrict__ V, float* __restrict__ out) {
    __shared__ __align__(16) char pool[8448];
    int tid = threadIdx.x;

    if (blockIdx.x < BH) {
        // ------------------- topk -------------------
        float* vals = (float*)pool;             // 2048 floats
        float* wv   = (float*)(pool + 8192);    // 8
        int*   wi   = (int*)(pool + 8224);      // 8
        int*   sel  = (int*)(pool + 8256);      // 40
        int bh = blockIdx.x;

        const float* pmx = g_pmx + (size_t)bh * NCH * L;
        const float* psm = g_psm + (size_t)bh * NCH * L;
        for (int i = tid; i < L; i += 256) {
            float mx = -1e30f, sm = 0.f;
            #pragma unroll
            for (int c = 0; c < NCH; c++) {
                mx = fmaxf(mx, pmx[c * L + i]);
                sm += psm[c * L + i];
            }
            vals[i] = mx - sm * (1.0f / (float)L);
        }
        __syncthreads();

        for (int t = 0; t < NTOP; t++) {
            float bv = -1e38f; int bi = 0;
            for (int i = tid; i < L; i += 256) {
                float v = vals[i];
                if (v > bv) { bv = v; bi = i; }
            }
            #pragma unroll
            for (int off = 16; off; off >>= 1) {
                float ov = __shfl_down_sync(FULLMASK, bv, off);
                int   oi = __shfl_down_sync(FULLMASK, bi, off);
                if (ov > bv || (ov == bv && oi < bi)) { bv = ov; bi = oi; }
            }
            if ((tid & 31) == 0) { wv[tid >> 5] = bv; wi[tid >> 5] = bi; }
            __syncthreads();
            if (tid == 0) {
                float fv = wv[0]; int fi = wi[0];
                #pragma unroll
                for (int ww = 1; ww < 8; ww++)
                    if (wv[ww] > fv || (wv[ww] == fv && wi[ww] < fi)) { fv = wv[ww]; fi = wi[ww]; }
                sel[t] = fi;
                vals[fi] = -1e38f;
            }
            __syncthreads();
        }

        if (tid < NTOP) {
            int mine = sel[tid], r = 0;
            #pragma unroll
            for (int i = 0; i < NTOP; i++) r += (sel[i] < mine);
            g_top[bh * NTOP + r] = mine;
        }
    } else {
        // ------------------- cumsumC -------------------
        float4 (*sp)[16] = (float4(*)[16])pool;            // [16][16]
        float4 (*sg)[16] = (float4(*)[16])(pool + 4096);   // [16][16]
        int cb = blockIdx.x - BH;
        int c = cb & (CCH - 1), bh = cb >> 6;
        int b = bh >> 3, h = bh & 7;
        int rg = tid >> 4, f4 = tid & 15;
        const int RS = H * D / 4;

        const float4* vb = (const float4*)(V + ((size_t)(b * L + c * CLEN + rg * 2) * H + h) * D) + f4;
        float4 v0 = vb[0], v1 = vb[RS];
        sp[rg][f4] = f4add(v0, v1);

        float4 gacc = make_float4(0.f, 0.f, 0.f, 0.f);
        const float4* cs4 = (const float4*)g_cs + (size_t)bh * CCH * 16 + f4;
        for (int cc = rg; cc < c; cc += 16) gacc = f4add(gacc, cs4[cc * 16]);
        sg[rg][f4] = gacc;
        __syncthreads();

        float4 run = make_float4(0.f, 0.f, 0.f, 0.f);
        #pragma unroll
        for (int i = 0; i < 16; i++) {
            run = f4add(run, sg[i][f4]);
            if (i < rg) run = f4add(run, sp[i][f4]);
        }

        float4 o0 = f4add(run, v0);
        float4 o1 = f4add(o0, v1);

        float4* ob = (float4*)(out + ((size_t)bh * L + c * CLEN + rg * 2) * D) + f4;
        ob[0] = o0; ob[16] = o1;
    }
}

// ---------------------------------------------------------------------------
// K3: attention partials, UNNORMALIZED exp (|s|<~6 so exp can't overflow;
// Σp·v/Σp identical to softmax). grid (KS, NU, BH). Causal early exit.
// ---------------------------------------------------------------------------
__global__ void __launch_bounds__(256)
attn_part_kernel(const float* __restrict__ Q,
                 const float* __restrict__ K,
                 const float* __restrict__ V) {
    int ks = blockIdx.x, uc = blockIdx.y, bh = blockIdx.z;
    int b = bh >> 3, h = bh & 7;
    int u0 = uc * UPC;

    int lu[UPC];
    #pragma unroll
    for (int iu = 0; iu < UPC; iu++) lu[iu] = g_top[bh * NTOP + u0 + iu];
    int lu_hi = lu[UPC - 1];
    if (ks * 256 > lu_hi) return;          // causal early exit

    int tid = threadIdx.x, w = tid >> 5, lane = tid & 31;
    int g = lane >> 3, j = lane & 7;

    float4 qa[UPC], qb[UPC];
    #pragma unroll
    for (int iu = 0; iu < UPC; iu++) {
        const float4* q4 = (const float4*)(Q + ((size_t)(b * L + lu[iu]) * H + h) * D);
        qa[iu] = q4[j]; qb[iu] = q4[8 + j];
    }

    float lsum[UPC];
    float4 aa[UPC], ab[UPC];
    #pragma unroll
    for (int iu = 0; iu < UPC; iu++) {
        lsum[iu] = 0.f;
        aa[iu] = make_float4(0.f, 0.f, 0.f, 0.f);
        ab[iu] = make_float4(0.f, 0.f, 0.f, 0.f);
    }

    int base = ks * 256 + w * 32;
    int nst = 0;
    if (base <= lu_hi) {
        int span = lu_hi + 1 - base;
        if (span > 32) span = 32;
        nst = (span + 3) >> 2;
    }

    const float* Kb = K + ((size_t)b * L * H + h) * D;
    const float* Vb = V + ((size_t)b * L * H + h) * D;

    for (int st = 0; st < nst; st++) {
        int t = base + st * 4 + g;
        const float4* k4 = (const float4*)(Kb + (size_t)t * H * D);
        const float4* v4 = (const float4*)(Vb + (size_t)t * H * D);
        float4 ka = k4[j], kb = k4[8 + j];
        float4 va = v4[j], vb = v4[8 + j];

        #pragma unroll
        for (int iu = 0; iu < UPC; iu++) {
            float d = qa[iu].x*ka.x + qa[iu].y*ka.y + qa[iu].z*ka.z + qa[iu].w*ka.w
                    + qb[iu].x*kb.x + qb[iu].y*kb.y + qb[iu].z*kb.z + qb[iu].w*kb.w;
            d += __shfl_xor_sync(FULLMASK, d, 4);
            d += __shfl_xor_sync(FULLMASK, d, 2);
            d += __shfl_xor_sync(FULLMASK, d, 1);
            float s = (t <= lu[iu]) ? d * 0.125f : -3e38f;
            float p = __expf(s);
            lsum[iu] += p;
            aa[iu].x += p * va.x; aa[iu].y += p * va.y;
            aa[iu].z += p * va.z; aa[iu].w += p * va.w;
            ab[iu].x += p * vb.x; ab[iu].y += p * vb.y;
            ab[iu].z += p * vb.z; ab[iu].w += p * vb.w;
        }
    }

    __shared__ float s_l[UPC][32];
    __shared__ float s_acc[UPC][32][64];
    int gs = w * 4 + g;
    #pragma unroll
    for (int iu = 0; iu < UPC; iu++) {
        if (j == 0) s_l[iu][gs] = lsum[iu];
        *(float4*)&s_acc[iu][gs][4 * j]      = aa[iu];
        *(float4*)&s_acc[iu][gs][32 + 4 * j] = ab[iu];
    }
    __syncthreads();

    for (int i = tid; i < UPC * 64; i += 256) {
        int iu = i >> 6, d = i & 63;
        float a = 0.f;
        #pragma unroll
        for (int gsi = 0; gsi < 32; gsi++) a += s_acc[iu][gsi][d];
        g_pacc[((size_t)(bh * NTOP + u0 + iu) * KS + ks) * D + d] = a;
    }
    if (tid < UPC) {
        float lt = 0.f;
        #pragma unroll
        for (int gsi = 0; gsi < 32; gsi++) lt += s_l[tid][gsi];
        g_pl[(size_t)(bh * NTOP + u0 + tid) * KS + ks] = lt;
    }
}

// ---------------------------------------------------------------------------
// K4: combine valid ks partials, normalize, scatter. grid (10, BH), 256 thr.
// ---------------------------------------------------------------------------
__global__ void __launch_bounds__(256)
attn_combine_kernel(float* __restrict__ out) {
    int bh = blockIdx.y;
    int tid = threadIdx.x;
    int u = blockIdx.x * 4 + (tid >> 6);
    int d = tid & 63;

    int uc = u / UPC;
    int lu_hi = g_top[bh * NTOP + uc * UPC + (UPC - 1)];
    int nks = (lu_hi >> 8) + 1;

    size_t base = (size_t)(bh * NTOP + u) * KS;
    float acc = 0.f, lt = 0.f;
    for (int p = 0; p < nks; p++) {
        acc += g_pacc[(base + p) * D + d];
        lt  += g_pl[base + p];
    }
    int lu = g_top[bh * NTOP + u];
    out[((size_t)bh * L + lu) * D + d] = acc / lt;
}

// ---------------------------------------------------------------------------
extern "C" void kernel_launch(void* const* d_in, const int* in_sizes, int n_in,
                              void* d_out, int out_size) {
    const float* Q   = (const float*)d_in[0];
    const float* K   = (const float*)d_in[1];
    const float* V   = (const float*)d_in[2];
    const int*   idx = (const int*)d_in[3];
    float*       out = (float*)d_out;

    const int KSMEM = 256 * D * sizeof(float);   // 64 KB
    cudaFuncSetAttribute(mscore2_kernel,
                         cudaFuncAttributeMaxDynamicSharedMemorySize, KSMEM);

    k0_binprep_cumsumA<<<NCH + CCH * BH / 2, 256>>>(idx, V);
    mscore2_kernel<<<dim3(NCH * NCH, BH), 256, KSMEM>>>(Q, K);
    k2_topk_cumsumC<<<BH + CCH * BH, 256>>>(V, out);
    attn_part_kernel<<<dim3(KS, NU, BH), 256>>>(Q, K, V);
    attn_combine_kernel<<<dim3(10, BH), 256>>>(out);
}

// round 17
// speedup vs baseline: 3.7627x; 3.7591x over previous
#include <cuda_runtime.h>

#define B 4
#define L 2048
#define H 8
#define D 64
#define S 40
#define NTOP 40
#define BH (B*H)

#define KS 8            // k-splits (256 keys each)
#define NU2 20          // u-chunks for attention
#define UPC 2           // u rows per chunk (NU2*UPC == NTOP)

#define CCH 64          // cumsum chunks
#define CLEN (L/CCH)    // 32 rows per chunk

#define MS_BLOCKS (BH*L/8)   // 8192 mscore blocks in K1
#define CA_BLOCKS (CCH*BH/2) // 1024 cumsumA blocks (2 chunks each) in K1

#define FULLMASK 0xffffffffu

// Scratch (no allocations allowed)
__device__ float g_M[BH * L];
__device__ int   g_top[BH * NTOP];
__device__ float g_cs[BH * CCH * D];
__device__ float g_pl[BH * NTOP * KS];
__device__ float g_pacc[BH * NTOP * KS * D];

__device__ __forceinline__ float4 f4add(float4 a, float4 b) {
    return make_float4(a.x + b.x, a.y + b.y, a.z + b.z, a.w + b.w);
}

// ---------------------------------------------------------------------------
// K1: fused mscore ∪ cumsumA (R12-verified). Role by blockIdx.x.
// mscore: one warp per (bh,l); coalesced group-gather, 8 lanes per sample,
// 4 samples per step. index_sample is int32 on the wire (JAX x64 downcast).
// ---------------------------------------------------------------------------
__global__ void __launch_bounds__(256)
k1_mscore_cumsumA(const float* __restrict__ Q,
                  const float* __restrict__ K,
                  const int* __restrict__ idx,
                  const float* __restrict__ V) {
    if (blockIdx.x < MS_BLOCKS) {
        // ------------------- mscore -------------------
        int warp = blockIdx.x * 8 + (threadIdx.x >> 5);
        int lane = threadIdx.x & 31;
        int g = lane >> 3, j = lane & 7;
        int l  = warp & (L - 1);
        int bh = warp >> 11;
        int b = bh >> 3, h = bh & 7;

        const float4* q4 = (const float4*)(Q + ((size_t)(b * L + l) * H + h) * D);
        float4 qa = q4[j], qb = q4[8 + j];

        const int* srow = idx + (size_t)l * S;
        int s_lo = srow[lane];
        int s_hi = (lane < 8) ? srow[lane + 32] : 0;

        const float* Kb = K + ((size_t)b * L * H + h) * D;
        float mx = -1e30f, sm = 0.f;

        #pragma unroll
        for (int bt = 0; bt < 10; bt++) {
            int s = bt * 4 + g;
            int ki = (bt < 8) ? __shfl_sync(FULLMASK, s_lo, s)
                              : __shfl_sync(FULLMASK, s_hi, s - 32);
            const float4* k4 = (const float4*)(Kb + (size_t)ki * H * D);
            float4 ka = k4[j], kb = k4[8 + j];
            float d = qa.x*ka.x + qa.y*ka.y + qa.z*ka.z + qa.w*ka.w
                    + qb.x*kb.x + qb.y*kb.y + qb.z*kb.z + qb.w*kb.w;
            d += __shfl_down_sync(FULLMASK, d, 4);
            d += __shfl_down_sync(FULLMASK, d, 2);
            d += __shfl_down_sync(FULLMASK, d, 1);
            if (j == 0) { mx = fmaxf(mx, d); sm += d; }
        }

        if (j != 0) { mx = -1e30f; sm = 0.f; }
        mx = fmaxf(mx, __shfl_xor_sync(FULLMASK, mx, 8));
        sm +=          __shfl_xor_sync(FULLMASK, sm, 8);
        mx = fmaxf(mx, __shfl_xor_sync(FULLMASK, mx, 16));
        sm +=          __shfl_xor_sync(FULLMASK, sm, 16);

        if (lane == 0) g_M[bh * L + l] = mx - sm * (1.0f / (float)L);
    } else {
        // ------------------- cumsumA -------------------
        __shared__ float4 sa[2][8][16];
        int cb = blockIdx.x - MS_BLOCKS;
        int tid = threadIdx.x;
        int half = tid >> 7;
        int t = tid & 127;
        int cc2 = cb * 2 + half;
        int c = cc2 & (CCH - 1), bh = cc2 >> 6;
        int b = bh >> 3, h = bh & 7;
        int rg = t >> 4, f4 = t & 15;
        const int RS = H * D / 4;

        const float4* vb = (const float4*)(V + ((size_t)(b * L + c * CLEN + rg * 4) * H + h) * D) + f4;
        float4 s = vb[0];
        #pragma unroll
        for (int i = 1; i < 4; i++) s = f4add(s, vb[(size_t)i * RS]);

        sa[half][rg][f4] = s;
        __syncthreads();
        if (rg == 0) {
            float4 tt = sa[half][0][f4];
            #pragma unroll
            for (int i = 1; i < 8; i++) tt = f4add(tt, sa[half][i][f4]);
            ((float4*)g_cs)[(bh * CCH + c) * 16 + f4] = tt;
        }
    }
}

// ---------------------------------------------------------------------------
// K2: fused topk ∪ cumsumC (R12-verified). Role by blockIdx.x.
// topk: top-40 of M, emitted ASCENDING (output order-invariant).
// ---------------------------------------------------------------------------
__global__ void __launch_bounds__(256)
k2_topk_cumsumC(const float* __restrict__ V, float* __restrict__ out) {
    __shared__ __align__(16) char pool[8448];
    int tid = threadIdx.x;

    if (blockIdx.x < BH) {
        // ------------------- topk -------------------
        float* vals = (float*)pool;             // 2048 floats
        float* wv   = (float*)(pool + 8192);    // 8
        int*   wi   = (int*)(pool + 8224);      // 8
        int*   sel  = (int*)(pool + 8256);      // 40
        int bh = blockIdx.x;

        for (int i = tid; i < L; i += 256) vals[i] = g_M[bh * L + i];
        __syncthreads();

        for (int t = 0; t < NTOP; t++) {
            float bv = -1e38f; int bi = 0;
            for (int i = tid; i < L; i += 256) {
                float v = vals[i];
                if (v > bv) { bv = v; bi = i; }
            }
            #pragma unroll
            for (int off = 16; off; off >>= 1) {
                float ov = __shfl_down_sync(FULLMASK, bv, off);
                int   oi = __shfl_down_sync(FULLMASK, bi, off);
                if (ov > bv || (ov == bv && oi < bi)) { bv = ov; bi = oi; }
            }
            if ((tid & 31) == 0) { wv[tid >> 5] = bv; wi[tid >> 5] = bi; }
            __syncthreads();
            if (tid == 0) {
                float fv = wv[0]; int fi = wi[0];
                #pragma unroll
                for (int w = 1; w < 8; w++)
                    if (wv[w] > fv || (wv[w] == fv && wi[w] < fi)) { fv = wv[w]; fi = wi[w]; }
                sel[t] = fi;
                vals[fi] = -1e38f;
            }
            __syncthreads();
        }

        if (tid < NTOP) {
            int mine = sel[tid], r = 0;
            #pragma unroll
            for (int i = 0; i < NTOP; i++) r += (sel[i] < mine);
            g_top[bh * NTOP + r] = mine;
        }
    } else {
        // ------------------- cumsumC -------------------
        float4 (*sp)[16] = (float4(*)[16])pool;            // [16][16]
        float4 (*sg)[16] = (float4(*)[16])(pool + 4096);   // [16][16]
        int cb = blockIdx.x - BH;
        int c = cb & (CCH - 1), bh = cb >> 6;
        int b = bh >> 3, h = bh & 7;
        int rg = tid >> 4, f4 = tid & 15;
        const int RS = H * D / 4;

        const float4* vb = (const float4*)(V + ((size_t)(b * L + c * CLEN + rg * 2) * H + h) * D) + f4;
        float4 v0 = vb[0], v1 = vb[RS];
        sp[rg][f4] = f4add(v0, v1);

        float4 gacc = make_float4(0.f, 0.f, 0.f, 0.f);
        const float4* cs4 = (const float4*)g_cs + (size_t)bh * CCH * 16 + f4;
        for (int cc = rg; cc < c; cc += 16) gacc = f4add(gacc, cs4[cc * 16]);
        sg[rg][f4] = gacc;
        __syncthreads();

        float4 run = make_float4(0.f, 0.f, 0.f, 0.f);
        #pragma unroll
        for (int i = 0; i < 16; i++) {
            run = f4add(run, sg[i][f4]);
            if (i < rg) run = f4add(run, sp[i][f4]);
        }

        float4 o0 = f4add(run, v0);
        float4 o1 = f4add(o0, v1);

        float4* ob = (float4*)(out + ((size_t)bh * L + c * CLEN + rg * 2) * D) + f4;
        ob[0] = o0; ob[16] = o1;
    }
}

// ---------------------------------------------------------------------------
// K3: attention partials, UPC=2 (register-pressure fix: live state 32 regs
// vs 80 at UPC=5 -> ~3 CTAs/SM instead of 2). UNNORMALIZED exp (|s|<~6, no
// overflow; Σp·v/Σp identical to softmax). grid (KS, NU2, BH); causal early
// exit per 2-u chunk (tighter lu_hi than 5-u chunks).
// ---------------------------------------------------------------------------
__global__ void __launch_bounds__(256)
attn_part_kernel(const float* __restrict__ Q,
                 const float* __restrict__ K,
                 const float* __restrict__ V) {
    int ks = blockIdx.x, uc = blockIdx.y, bh = blockIdx.z;
    int b = bh >> 3, h = bh & 7;
    int u0 = uc * UPC;

    int lu[UPC];
    #pragma unroll
    for (int iu = 0; iu < UPC; iu++) lu[iu] = g_top[bh * NTOP + u0 + iu];
    int lu_hi = lu[UPC - 1];
    if (ks * 256 > lu_hi) return;          // causal early exit

    int tid = threadIdx.x, w = tid >> 5, lane = tid & 31;
    int g = lane >> 3, j = lane & 7;

    float4 qa[UPC], qb[UPC];
    #pragma unroll
    for (int iu = 0; iu < UPC; iu++) {
        const float4* q4 = (const float4*)(Q + ((size_t)(b * L + lu[iu]) * H + h) * D);
        qa[iu] = q4[j]; qb[iu] = q4[8 + j];
    }

    float lsum[UPC];
    float4 aa[UPC], ab[UPC];
    #pragma unroll
    for (int iu = 0; iu < UPC; iu++) {
        lsum[iu] = 0.f;
        aa[iu] = make_float4(0.f, 0.f, 0.f, 0.f);
        ab[iu] = make_float4(0.f, 0.f, 0.f, 0.f);
    }

    int base = ks * 256 + w * 32;
    int nst = 0;
    if (base <= lu_hi) {
        int span = lu_hi + 1 - base;
        if (span > 32) span = 32;
        nst = (span + 3) >> 2;
    }

    const float* Kb = K + ((size_t)b * L * H + h) * D;
    const float* Vb = V + ((size_t)b * L * H + h) * D;

    for (int st = 0; st < nst; st++) {
        int t = base + st * 4 + g;
        const float4* k4 = (const float4*)(Kb + (size_t)t * H * D);
        const float4* v4 = (const float4*)(Vb + (size_t)t * H * D);
        float4 ka = k4[j], kb = k4[8 + j];
        float4 va = v4[j], vb = v4[8 + j];

        #pragma unroll
        for (int iu = 0; iu < UPC; iu++) {
            float d = qa[iu].x*ka.x + qa[iu].y*ka.y + qa[iu].z*ka.z + qa[iu].w*ka.w
                    + qb[iu].x*kb.x + qb[iu].y*kb.y + qb[iu].z*kb.z + qb[iu].w*kb.w;
            d += __shfl_xor_sync(FULLMASK, d, 4);
            d += __shfl_xor_sync(FULLMASK, d, 2);
            d += __shfl_xor_sync(FULLMASK, d, 1);
            float s = (t <= lu[iu]) ? d * 0.125f : -3e38f;
            float p = __expf(s);
            lsum[iu] += p;
            aa[iu].x += p * va.x; aa[iu].y += p * va.y;
            aa[iu].z += p * va.z; aa[iu].w += p * va.w;
            ab[iu].x += p * vb.x; ab[iu].y += p * vb.y;
            ab[iu].z += p * vb.z; ab[iu].w += p * vb.w;
        }
    }

    __shared__ float s_l[UPC][32];
    __shared__ float s_acc[UPC][32][64];
    int gs = w * 4 + g;
    #pragma unroll
    for (int iu = 0; iu < UPC; iu++) {
        if (j == 0) s_l[iu][gs] = lsum[iu];
        *(float4*)&s_acc[iu][gs][4 * j]      = aa[iu];
        *(float4*)&s_acc[iu][gs][32 + 4 * j] = ab[iu];
    }
    __syncthreads();

    for (int i = tid; i < UPC * 64; i += 256) {
        int iu = i >> 6, d = i & 63;
        float a = 0.f;
        #pragma unroll
        for (int gsi = 0; gsi < 32; gsi++) a += s_acc[iu][gsi][d];
        g_pacc[((size_t)(bh * NTOP + u0 + iu) * KS + ks) * D + d] = a;
    }
    if (tid < UPC) {
        float lt = 0.f;
        #pragma unroll
        for (int gsi = 0; gsi < 32; gsi++) lt += s_l[tid][gsi];
        g_pl[(size_t)(bh * NTOP + u0 + tid) * KS + ks] = lt;
    }
}

// ---------------------------------------------------------------------------
// K4: combine valid ks partials, normalize, scatter. grid (10, BH), 256 thr;
// uc = u/UPC matches the 2-u chunking of K3.
// ---------------------------------------------------------------------------
__global__ void __launch_bounds__(256)
attn_combine_kernel(float* __restrict__ out) {
    int bh = blockIdx.y;
    int tid = threadIdx.x;
    int u = blockIdx.x * 4 + (tid >> 6);
    int d = tid & 63;

    int uc = u / UPC;
    int lu_hi = g_top[bh * NTOP + uc * UPC + (UPC - 1)];
    int nks = (lu_hi >> 8) + 1;

    size_t base = (size_t)(bh * NTOP + u) * KS;
    float acc = 0.f, lt = 0.f;
    for (int p = 0; p < nks; p++) {
        acc += g_pacc[(base + p) * D + d];
        lt  += g_pl[base + p];
    }
    int lu = g_top[bh * NTOP + u];
    out[((size_t)bh * L + lu) * D + d] = acc / lt;
}

// ---------------------------------------------------------------------------
extern "C" void kernel_launch(void* const* d_in, const int* in_sizes, int n_in,
                              void* d_out, int out_size) {
    const float* Q   = (const float*)d_in[0];
    const float* K   = (const float*)d_in[1];
    const float* V   = (const float*)d_in[2];
    const int*   idx = (const int*)d_in[3];
    float*       out = (float*)d_out;

    k1_mscore_cumsumA<<<MS_BLOCKS + CA_BLOCKS, 256>>>(Q, K, idx, V);
    k2_topk_cumsumC  <<<BH + CCH * BH, 256>>>(V, out);
    attn_part_kernel <<<dim3(KS, NU2, BH), 256>>>(Q, K, V);
    attn_combine_kernel<<<dim3(10, BH), 256>>>(out);
}